// round 1
// baseline (speedup 1.0000x reference)
#include <cuda_runtime.h>
#include <cstdint>

// NearestEmbed: x [B=32, D=128, H=64, W=64] f32, weight [D=128, K=1024] f32
// out = concat( result[B,D,H,W] (gathered codebook rows), argmin[B,H,W] as f32 )
//
// d2 = (x2 - 2*xe) + e2 with fp32 rounding mimicking the jax reference:
//   x2: sequential sum over d of round(x*x)   (separate mul/add rounding)
//   e2: sequential sum over d of round(w*w)
//   xe: fp32 dot (FMA ok; error ~1e-9, far below the d2 ulp grid ~7.6e-6)
// argmin tie-break: first (lowest) index, via strict '<' ascending k and a
// packed (d2_bits<<32 | k) atomicMin (positive f32 bits are order-preserving).

#define DCH 128
#define KCODES 1024
#define HW 4096
#define BATCH 32
#define MTILE 128
#define NTILE 128
#define NSTAGES (KCODES / NTILE)
#define RES_ELEMS ((size_t)BATCH * DCH * HW)   // 16777216

__global__ __launch_bounds__(256, 1)
void nearest_embed_kernel(const float* __restrict__ x,
                          const float* __restrict__ w,
                          float* __restrict__ out,
                          int write_amin) {
    extern __shared__ float smem[];
    float* xs  = smem;                       // [D][MTILE]
    float* ws  = smem + DCH * MTILE;         // [D][NTILE]
    float* x2s = ws + DCH * NTILE;           // [MTILE]
    float* e2s = x2s + MTILE;                // [NTILE]
    unsigned long long* best =
        (unsigned long long*)(e2s + NTILE);  // [MTILE], 8B-aligned (33024 f32s)

    const int tid  = threadIdx.x;
    const int tile = blockIdx.x;             // 0..1023
    const int b    = tile >> 5;              // 4096/128 = 32 tiles per image
    const int hw0  = (tile & 31) * MTILE;

    if (tid < MTILE) best[tid] = 0xFFFFFFFFFFFFFFFFull;

    // ---- load x tile [D][MTILE] (coalesced float4) ----
    const float* xbase = x + ((size_t)b * DCH) * HW + hw0;
    for (int i = tid; i < DCH * (MTILE / 4); i += 256) {
        int d = i >> 5;                      // MTILE/4 = 32 float4 per d-row
        int s = i & 31;
        float4 v = *reinterpret_cast<const float4*>(xbase + (size_t)d * HW + s * 4);
        *reinterpret_cast<float4*>(xs + d * MTILE + s * 4) = v;
    }
    __syncthreads();

    // ---- x2 per pixel: sequential over d, separate mul/add rounding ----
    if (tid < MTILE) {
        float acc = 0.0f;
        for (int d = 0; d < DCH; ++d) {
            float v = xs[d * MTILE + tid];
            acc = __fadd_rn(acc, __fmul_rn(v, v));
        }
        x2s[tid] = acc;
    }

    const int tx  = tid & 15;
    const int ty  = tid >> 4;
    const int px0 = ty * 8;
    const int c0  = tx * 8;

    float acc[8][8];

    for (int kt = 0; kt < NSTAGES; ++kt) {
        __syncthreads();   // epilogue of prev stage done; x2s visible (kt=0)

        // ---- load w tile [D][NTILE], codes kt*128 .. ----
        const float* wbase = w + kt * NTILE;
        for (int i = tid; i < DCH * (NTILE / 4); i += 256) {
            int d = i >> 5;
            int s = i & 31;
            float4 v = *reinterpret_cast<const float4*>(wbase + d * KCODES + s * 4);
            *reinterpret_cast<float4*>(ws + d * NTILE + s * 4) = v;
        }
        __syncthreads();

        // ---- e2 for this code tile: sequential over d ----
        if (tid < NTILE) {
            float a2 = 0.0f;
            for (int d = 0; d < DCH; ++d) {
                float v = ws[d * NTILE + tid];
                a2 = __fadd_rn(a2, __fmul_rn(v, v));
            }
            e2s[tid] = a2;
        }

        #pragma unroll
        for (int i = 0; i < 8; ++i)
            #pragma unroll
            for (int j = 0; j < 8; ++j) acc[i][j] = 0.0f;

        // ---- main D loop: 8x8 register tile, 64 FFMA per 4 LDS.128 ----
        #pragma unroll 4
        for (int d = 0; d < DCH; ++d) {
            const float4 a0 = *reinterpret_cast<const float4*>(xs + d * MTILE + px0);
            const float4 a1 = *reinterpret_cast<const float4*>(xs + d * MTILE + px0 + 4);
            const float4 b0 = *reinterpret_cast<const float4*>(ws + d * NTILE + c0);
            const float4 b1 = *reinterpret_cast<const float4*>(ws + d * NTILE + c0 + 4);
            const float xa[8] = {a0.x, a0.y, a0.z, a0.w, a1.x, a1.y, a1.z, a1.w};
            const float wb[8] = {b0.x, b0.y, b0.z, b0.w, b1.x, b1.y, b1.z, b1.w};
            #pragma unroll
            for (int i = 0; i < 8; ++i)
                #pragma unroll
                for (int j = 0; j < 8; ++j)
                    acc[i][j] = fmaf(xa[i], wb[j], acc[i][j]);
        }
        __syncthreads();   // e2s writes visible before epilogue reads

        // ---- epilogue: d2 = (x2 - 2*xe) + e2, first-min tie-break ----
        #pragma unroll
        for (int i = 0; i < 8; ++i) {
            const float x2v = x2s[px0 + i];
            float bd = __int_as_float(0x7F800000);  // +inf
            int   bj = 0;
            #pragma unroll
            for (int j = 0; j < 8; ++j) {
                float t  = __fadd_rn(x2v, __fmul_rn(-2.0f, acc[i][j]));
                float d2 = __fadd_rn(t, e2s[c0 + j]);
                if (d2 < bd) { bd = d2; bj = j; }
            }
            unsigned long long pack =
                ((unsigned long long)__float_as_uint(bd) << 32) |
                (unsigned)(kt * NTILE + c0 + bj);
            atomicMin(&best[px0 + i], pack);
        }
    }
    __syncthreads();

    // ---- write result: out[b,d,h,w] = weight[d, argmin] ----
    const size_t obase = ((size_t)b * DCH) * HW + hw0;
    for (int i = tid; i < DCH * MTILE; i += 256) {
        int d  = i >> 7;
        int px = i & 127;
        unsigned k = (unsigned)(best[px] & 0xFFFFFFFFu);
        out[obase + (size_t)d * HW + px] = w[d * KCODES + k];
    }
    // ---- write argmin (as f32) if the output buffer includes it ----
    if (write_amin && tid < MTILE) {
        unsigned k = (unsigned)(best[tid] & 0xFFFFFFFFu);
        out[RES_ELEMS + (size_t)b * HW + hw0 + tid] = (float)k;
    }
}

extern "C" void kernel_launch(void* const* d_in, const int* in_sizes, int n_in,
                              void* d_out, int out_size) {
    const float* x = (const float*)d_in[0];
    const float* w = (const float*)d_in[1];
    float* out = (float*)d_out;

    const int write_amin = ((size_t)out_size > RES_ELEMS) ? 1 : 0;

    const int smem_bytes =
        (DCH * MTILE + DCH * NTILE + MTILE + NTILE) * (int)sizeof(float) +
        MTILE * (int)sizeof(unsigned long long);   // 133120 B

    cudaFuncSetAttribute(nearest_embed_kernel,
                         cudaFuncAttributeMaxDynamicSharedMemorySize, smem_bytes);

    nearest_embed_kernel<<<(BATCH * HW) / MTILE, 256, smem_bytes>>>(x, w, out, write_amin);
}

// round 5
// speedup vs baseline: 1.1853x; 1.1853x over previous
#include <cuda_runtime.h>
#include <cstdint>

// NearestEmbed, packed-f32x2 SIMT GEMM + fused argmin.
// Arithmetic bit-identical to the R1 kernel (rel_err 0.0):
//   xe[px,k]: fp32 fma chain over d ascending (f32x2 packed = same per-lane rounding)
//   x2/e2:    sequential fadd(rn(v*v)) over d ascending
//   d2 = fadd(fadd(x2, fmul(-2,xe)), e2); first-index tie-break via packed atomicMin.
// R5 fix: injective shared-mem swizzle for the w tile (R4's overlapped -> corrupt).

#define DCH 128
#define KCODES 1024
#define HW 4096
#define BATCH 32
#define RES_ELEMS ((size_t)BATCH * DCH * HW)

#define MTILE 128          // pixels per CTA
#define NSTAGE 256         // codes per stage
#define NPHASES 8          // 4 stages x 2 d-chunks of 64
#define WROW 1136          // bytes per d-row: 71 slots x 16B (64 granules + pads)
#define WSBUF (64 * WROW)  // 72704 bytes per chunk buffer

#define OFF_XS 0                       // [128d][128px] f32 = 65536
#define OFF_WS 65536                   // 2 x WSBUF = 145408
#define OFF_X2 210944                  // 128 f32
#define OFF_E2 211456                  // 256 f32
#define OFF_BEST 212480                // 128 u64
#define SMEM_TOTAL 213504

__device__ __forceinline__ uint32_t smem_u32(const void* p) {
    uint32_t a;
    asm("{ .reg .u64 t; cvta.to.shared.u64 t, %1; cvt.u32.u64 %0, t; }" : "=r"(a) : "l"(p));
    return a;
}
__device__ __forceinline__ void cp16(uint32_t dst, const void* src) {
    asm volatile("cp.async.cg.shared.global [%0], [%1], 16;" :: "r"(dst), "l"(src) : "memory");
}
#define CP_COMMIT() asm volatile("cp.async.commit_group;" ::: "memory")
#define CP_WAIT(N)  asm volatile("cp.async.wait_group %0;" :: "n"(N) : "memory")

#define FMA2(A, X, W) \
    asm("fma.rn.f32x2 %0, %1, %2, %3;" : "=l"(A) : "l"(X), "l"(W), "l"(A))
#define DUP2(D, F) \
    asm("mov.b64 %0, {%1, %1};" : "=l"(D) : "r"(__float_as_uint(F)))
#define UNPK(LO, HI, P) \
    asm("mov.b64 {%0, %1}, %2;" : "=r"(LO), "=r"(HI) : "l"(P))

// injective granule swizzle: granule q (16B) of a d-row -> byte (q + (q>>3)) * 16
__device__ __forceinline__ uint32_t granule_off(uint32_t q) {
    return (q + (q >> 3)) << 4;
}
// byte offset of 16-code group tx (granules 4tx..4tx+3, always contiguous 64B)
__device__ __forceinline__ uint32_t group_off(uint32_t tx) {
    return tx * 64u + (tx >> 1) * 16u;
}

__global__ __launch_bounds__(256, 1)
void nearest_embed_f32x2_kernel(const float* __restrict__ x,
                                const float* __restrict__ w,
                                float* __restrict__ out,
                                int write_amin) {
    extern __shared__ char smem[];
    const uint32_t su = smem_u32(smem);
    const int tid = threadIdx.x;
    const int blk = blockIdx.x;
    const int b = blk >> 5;
    const int hw0 = (blk & 31) * MTILE;

    float* x2s = (float*)(smem + OFF_X2);
    float* e2s = (float*)(smem + OFF_E2);
    unsigned long long* best = (unsigned long long*)(smem + OFF_BEST);

    const int tx = tid & 15;           // code group (16 codes)
    const int ty = tid >> 4;           // pixel group (8 px)
    const int px0 = ty * 8;

    if (tid < MTILE) best[tid] = 0xFFFFFFFFFFFFFFFFull;

    // ---- async load x tile [128d][128px] ----
    const float* xbase = x + ((size_t)b * DCH) * HW + hw0;
    for (int t = tid; t < DCH * 32; t += 256) {      // 32 float4 per d-row
        int d = t >> 5, q = t & 31;
        cp16(su + OFF_XS + (uint32_t)(d * 512 + q * 16),
             xbase + (size_t)d * HW + q * 4);
    }
    CP_COMMIT();

    // ---- async load ws chunks 0 and 1 (stage 0) ----
    for (int cc = 0; cc < 2; ++cc) {
        const float* src = w + (size_t)(cc * 64) * KCODES;   // stage 0, codes 0..255
        uint32_t dbuf = su + OFF_WS + cc * WSBUF;
        for (int t = tid; t < 4096; t += 256) {              // 64 rows x 64 granules
            int dr = t >> 6, q = t & 63;
            cp16(dbuf + (uint32_t)(dr * WROW) + granule_off((uint32_t)q),
                 src + (size_t)dr * KCODES + q * 4);
        }
        CP_COMMIT();
    }

    // ---- x2 (needs xs only) ----
    CP_WAIT(2);
    __syncthreads();
    if (tid < MTILE) {
        const float* col = (const float*)(smem + OFF_XS) + tid;
        float a = 0.0f;
        for (int d = 0; d < DCH; ++d) {
            float v = col[d * MTILE];
            a = __fadd_rn(a, __fmul_rn(v, v));
        }
        x2s[tid] = a;
    }
    __syncthreads();

    float x2v[8];
#pragma unroll
    for (int i = 0; i < 8; ++i) x2v[i] = x2s[px0 + i];

    unsigned long long acc[8][8];
    float bd[8];
    int bk[8];
#pragma unroll
    for (int i = 0; i < 8; ++i) { bd[i] = __int_as_float(0x7F800000); bk[i] = 0; }

    const uint32_t wsel = group_off((uint32_t)tx);   // this thread's code-group offset
    const uint32_t e2off = granule_off((uint32_t)(tid >> 2)) + (tid & 3) * 4;

    for (int m = 0; m < NPHASES; ++m) {
        // ---- wait for chunk m ----
        if (m < NPHASES - 1) { CP_WAIT(1); } else { CP_WAIT(0); }
        __syncthreads();

        const char* buf = smem + OFF_WS + (m & 1) * WSBUF;

        // ---- e2 partial for this chunk (thread tid -> stage-local code tid) ----
        {
            float a = (m & 1) ? e2s[tid] : 0.0f;
            const char* p = buf + e2off;
#pragma unroll 4
            for (int dr = 0; dr < 64; ++dr) {
                float v = *(const float*)(p + dr * WROW);
                a = __fadd_rn(a, __fmul_rn(v, v));
            }
            e2s[tid] = a;
        }

        // ---- main FMA: 64 d-steps, 8px x 16codes per thread ----
        if ((m & 1) == 0) {
#pragma unroll
            for (int i = 0; i < 8; ++i)
#pragma unroll
                for (int jp = 0; jp < 8; ++jp) acc[i][jp] = 0ull;
        }
        {
            const char* wb = buf + wsel;
            const char* xb = smem + OFF_XS + (m & 1) * (64 * 512) + px0 * 4;
#pragma unroll 4
            for (int dr = 0; dr < 64; ++dr) {
                const ulonglong2 w0 = *(const ulonglong2*)(wb + dr * WROW);
                const ulonglong2 w1 = *(const ulonglong2*)(wb + dr * WROW + 16);
                const ulonglong2 w2 = *(const ulonglong2*)(wb + dr * WROW + 32);
                const ulonglong2 w3 = *(const ulonglong2*)(wb + dr * WROW + 48);
                const float4 xa = *(const float4*)(xb + dr * 512);
                const float4 xc = *(const float4*)(xb + dr * 512 + 16);
                const float xf[8] = {xa.x, xa.y, xa.z, xa.w, xc.x, xc.y, xc.z, xc.w};
                const unsigned long long wd[8] = {w0.x, w0.y, w1.x, w1.y,
                                                  w2.x, w2.y, w3.x, w3.y};
                unsigned long long xd[8];
#pragma unroll
                for (int i = 0; i < 8; ++i) DUP2(xd[i], xf[i]);
#pragma unroll
                for (int i = 0; i < 8; ++i)
#pragma unroll
                    for (int jp = 0; jp < 8; ++jp)
                        FMA2(acc[i][jp], xd[i], wd[jp]);
            }
        }

        __syncthreads();   // all reads of buf done; e2s visible

        // ---- prefetch chunk m+2 into buf(m&1) ----
        if (m < NPHASES - 2) {
            const int mp = m + 2;
            const int s2 = mp >> 1, cc2 = mp & 1;
            const float* src = w + (size_t)(cc2 * 64) * KCODES + s2 * NSTAGE;
            uint32_t dbuf = su + OFF_WS + (m & 1) * WSBUF;
            for (int t = tid; t < 4096; t += 256) {
                int dr = t >> 6, q = t & 63;
                cp16(dbuf + (uint32_t)(dr * WROW) + granule_off((uint32_t)q),
                     src + (size_t)dr * KCODES + q * 4);
            }
            CP_COMMIT();
        }

        // ---- stage epilogue after second chunk ----
        if (m & 1) {
            const int kbase = (m >> 1) * NSTAGE + tx * 16;
#pragma unroll
            for (int i = 0; i < 8; ++i) {
                const float xv = x2v[i];
#pragma unroll
                for (int jp = 0; jp < 8; ++jp) {
                    uint32_t lo, hi;
                    UNPK(lo, hi, acc[i][jp]);
                    float xel = __uint_as_float(lo);
                    float t0 = __fadd_rn(xv, __fmul_rn(-2.0f, xel));
                    float d2l = __fadd_rn(t0, e2s[tx * 16 + 2 * jp]);
                    if (d2l < bd[i]) { bd[i] = d2l; bk[i] = kbase + 2 * jp; }
                    float xeh = __uint_as_float(hi);
                    float t1 = __fadd_rn(xv, __fmul_rn(-2.0f, xeh));
                    float d2h = __fadd_rn(t1, e2s[tx * 16 + 2 * jp + 1]);
                    if (d2h < bd[i]) { bd[i] = d2h; bk[i] = kbase + 2 * jp + 1; }
                }
            }
        }
    }

    // ---- merge across the 16 threads sharing each pixel ----
#pragma unroll
    for (int i = 0; i < 8; ++i) {
        unsigned long long pack =
            ((unsigned long long)__float_as_uint(bd[i]) << 32) | (unsigned)bk[i];
        atomicMin(&best[px0 + i], pack);
    }
    __syncthreads();

    // ---- outputs: gather codebook rows + argmin ----
    const size_t obase = ((size_t)b * DCH) * HW + hw0;
    for (int t = tid; t < DCH * MTILE; t += 256) {
        int d = t >> 7;
        int px = t & 127;
        unsigned k = (unsigned)(best[px] & 0xFFFFFFFFu);
        out[obase + (size_t)d * HW + px] = w[(size_t)d * KCODES + k];
    }
    if (write_amin && tid < MTILE) {
        unsigned k = (unsigned)(best[tid] & 0xFFFFFFFFu);
        out[RES_ELEMS + (size_t)b * HW + hw0 + tid] = (float)k;
    }
}

extern "C" void kernel_launch(void* const* d_in, const int* in_sizes, int n_in,
                              void* d_out, int out_size) {
    const float* x = (const float*)d_in[0];
    const float* w = (const float*)d_in[1];
    float* out = (float*)d_out;
    const int write_amin = ((size_t)out_size > RES_ELEMS) ? 1 : 0;

    cudaFuncSetAttribute(nearest_embed_f32x2_kernel,
                         cudaFuncAttributeMaxDynamicSharedMemorySize, SMEM_TOTAL);
    nearest_embed_f32x2_kernel<<<(BATCH * HW) / MTILE, 256, SMEM_TOTAL>>>(
        x, w, out, write_amin);
}